// round 1
// baseline (speedup 1.0000x reference)
#include <cuda_runtime.h>

// ============================================================================
// STGCNEncoder — only row 0 of the GCN output feeds the GRU, so we compute
// exactly that: collect edges into node 0 (~32 of 3.2M), exact degrees for
// the ~34-node involved set via a membership pass, then tiny fused GEMVs.
// ============================================================================

#define CAP 2048  // capacity for dst==0 edge list (expected ~32, Poisson)

__device__ int   g_is64;            // 1 if edge_index is int64, 0 if int32
__device__ int   g_cnt;             // number of dst==0 edges collected
__device__ int   g_srcs[CAP];       // src node of each dst==0 edge
__device__ int   g_counts[CAP + 1]; // in-degree (edge count) per set entry; [cnt] = node 0
__device__ float g_g0[128];         // relu(agg[0] + b_gcn)
__device__ float g_gi[768];
__device__ float g_gh[768];

// ---------------------------------------------------------------------------
__global__ void k_reset() {
    int t = threadIdx.x;
    if (t == 0) { g_cnt = 0; g_is64 = 1; }
    for (int i = t; i < CAP + 1; i += blockDim.x) g_counts[i] = 0;
}

// Detect dtype: if data is int64 (values < 1e5 >= 0), every odd 32-bit word
// is 0. If int32, odd words are random node ids — some nonzero w.p. ~1.
__global__ void k_detect(const int* __restrict__ w, int E) {
    int i = threadIdx.x;  // check values 0..511 (well within E)
    int bad = 0;
    if (w[2 * i + 1] != 0) bad = 1;
    if (w[2 * (i + 256) + 1] != 0) bad = 1;
    if (bad) atomicAnd(&g_is64, 0);
}

// Pass 1: stream dst array, collect src of edges with dst == 0.
__global__ void k_collect(const int* __restrict__ w, int E) {
    int is64 = g_is64;
    long gid = (long)blockIdx.x * blockDim.x + threadIdx.x;
    long stride = (long)gridDim.x * blockDim.x;
    if (is64) {
        const long long* src = (const long long*)w;
        const long long* dst = src + E;
        for (long i = gid; i < E; i += stride) {
            if (dst[i] == 0) {
                int p = atomicAdd(&g_cnt, 1);
                if (p < CAP) g_srcs[p] = (int)src[i];
            }
        }
    } else {
        const int* src = w;
        const int* dst = w + E;
        for (long i = gid; i < E; i += stride) {
            if (dst[i] == 0) {
                int p = atomicAdd(&g_cnt, 1);
                if (p < CAP) g_srcs[p] = src[i];
            }
        }
    }
}

// Pass 2: membership count — exact in-degree (dst occurrence count) for every
// entry in the set {srcs} ∪ {0}. Entry index cnt is node 0.
// Duplicated src entries each get their own (identical) count — required,
// since each edge contributes its own norm*x[src] term.
__global__ void k_count(const int* __restrict__ w, int E) {
    __shared__ int sh_set[CAP + 1];
    __shared__ int sh_m;
    int t = threadIdx.x;
    if (t == 0) {
        int c = g_cnt; if (c > CAP) c = CAP;
        sh_m = c + 1;
    }
    __syncthreads();
    int M = sh_m;
    for (int j = t; j < M; j += blockDim.x)
        sh_set[j] = (j < M - 1) ? g_srcs[j] : 0;
    __syncthreads();

    int is64 = g_is64;
    long gid = (long)blockIdx.x * blockDim.x + t;
    long stride = (long)gridDim.x * blockDim.x;
    if (is64) {
        const long long* dst = ((const long long*)w) + E;
        for (long i = gid; i < E; i += stride) {
            int d = (int)dst[i];
            for (int j = 0; j < M; j++)
                if (d == sh_set[j]) atomicAdd(&g_counts[j], 1);
        }
    } else {
        const int* dst = w + E;
        for (long i = gid; i < E; i += stride) {
            int d = dst[i];
            for (int j = 0; j < M; j++)
                if (d == sh_set[j]) atomicAdd(&g_counts[j], 1);
        }
    }
}

// Encoder + weighted sum + GCN GEMV for row 0. Single block, 256 threads.
// xsum = sum_i w_i * relu(W_enc @ f[s_i] + b_enc),  w_i = rsqrt(deg_i)*rsqrt(deg_0)
// g0 = relu(W_gcn @ xsum + b_gcn)
__global__ void k_gcn(const float* __restrict__ nf,
                      const float* __restrict__ W_enc,
                      const float* __restrict__ b_enc,
                      const float* __restrict__ W_gcn,
                      const float* __restrict__ b_gcn) {
    __shared__ float sWe[128 * 65];   // W_enc padded (stride 65 -> conflict-free)
    __shared__ float sPart[8][128];   // per-warp partial xsum
    __shared__ float sF[8][64];       // per-warp node feature buffer
    __shared__ float sXsum[128];
    __shared__ float sBenc[128];

    int t = threadIdx.x, lane = t & 31, w = t >> 5;

    for (int i = t; i < 128 * 64; i += 256) {
        int j = i >> 6, k = i & 63;
        sWe[j * 65 + k] = W_enc[i];
    }
    if (t < 128) sBenc[t] = b_enc[t];
    for (int i = t; i < 8 * 128; i += 256) ((float*)sPart)[i] = 0.0f;
    __syncthreads();

    int cnt = g_cnt; if (cnt > CAP) cnt = CAP;
    int M = cnt + 1;
    float dinv0 = rsqrtf((float)g_counts[cnt] + 1.0f);  // +1 self loop

    for (int i = w; i < M; i += 8) {
        int s = (i < cnt) ? g_srcs[i] : 0;
        float wt = rsqrtf((float)g_counts[i] + 1.0f) * dinv0;
        sF[w][lane]      = nf[(long)s * 64 + lane];
        sF[w][lane + 32] = nf[(long)s * 64 + 32 + lane];
        __syncwarp();
        #pragma unroll
        for (int jj = 0; jj < 4; jj++) {
            int j = jj * 32 + lane;
            float acc = sBenc[j];
            const float* wr = &sWe[j * 65];
            #pragma unroll
            for (int k = 0; k < 64; k++) acc += wr[k] * sF[w][k];
            sPart[w][j] += wt * fmaxf(acc, 0.0f);
        }
        __syncwarp();
    }
    __syncthreads();

    if (t < 128) {
        float xs = 0.0f;
        #pragma unroll
        for (int ww = 0; ww < 8; ww++) xs += sPart[ww][t];
        sXsum[t] = xs;
    }
    __syncthreads();

    // GCN GEMV: warp per output row, coalesced W_gcn reads + shuffle reduce
    for (int j = w; j < 128; j += 8) {
        float a = 0.0f;
        #pragma unroll
        for (int kk = 0; kk < 4; kk++) {
            int k = kk * 32 + lane;
            a += W_gcn[j * 128 + k] * sXsum[k];
        }
        #pragma unroll
        for (int off = 16; off; off >>= 1) a += __shfl_down_sync(0xffffffffu, a, off);
        if (lane == 0) g_g0[j] = fmaxf(a + b_gcn[j], 0.0f);
    }
}

// GRU GEMVs: 1536 warp-tasks (768 rows of W_ih@g0, 768 rows of W_hh@h).
__global__ void k_gru(const float* __restrict__ W_ih,
                      const float* __restrict__ W_hh,
                      const float* __restrict__ b_ih,
                      const float* __restrict__ b_hh,
                      const float* __restrict__ h) {
    __shared__ float sg0[128];
    int t = threadIdx.x, lane = t & 31, w = t >> 5;
    if (t < 128) sg0[t] = g_g0[t];
    __syncthreads();

    int task = blockIdx.x * 8 + w;
    if (task < 768) {
        const float* wr = W_ih + task * 128;
        float a = 0.0f;
        #pragma unroll
        for (int kk = 0; kk < 4; kk++) {
            int k = kk * 32 + lane;
            a += wr[k] * sg0[k];
        }
        #pragma unroll
        for (int off = 16; off; off >>= 1) a += __shfl_down_sync(0xffffffffu, a, off);
        if (lane == 0) g_gi[task] = a + b_ih[task];
    } else {
        int r = task - 768;
        const float* wr = W_hh + r * 256;
        float a = 0.0f;
        #pragma unroll
        for (int kk = 0; kk < 8; kk++) {
            int k = kk * 32 + lane;
            a += wr[k] * h[k];
        }
        #pragma unroll
        for (int off = 16; off; off >>= 1) a += __shfl_down_sync(0xffffffffu, a, off);
        if (lane == 0) g_gh[r] = a + b_hh[r];
    }
}

// Final gates.
__global__ void k_out(const float* __restrict__ h, float* __restrict__ out) {
    int c = threadIdx.x;
    float r  = 1.0f / (1.0f + expf(-(g_gi[c]       + g_gh[c])));
    float z  = 1.0f / (1.0f + expf(-(g_gi[256 + c] + g_gh[256 + c])));
    float nn = tanhf(g_gi[512 + c] + r * g_gh[512 + c]);
    out[c] = (1.0f - z) * nn + z * h[c];
}

// ---------------------------------------------------------------------------
extern "C" void kernel_launch(void* const* d_in, const int* in_sizes, int n_in,
                              void* d_out, int out_size) {
    const float* nf    = (const float*)d_in[0];
    // d_in[1] = edge_attr (unused by reference)
    const float* h     = (const float*)d_in[2];
    const float* W_enc = (const float*)d_in[3];
    const float* b_enc = (const float*)d_in[4];
    const float* W_gcn = (const float*)d_in[5];
    const float* b_gcn = (const float*)d_in[6];
    const float* W_ih  = (const float*)d_in[7];
    const float* W_hh  = (const float*)d_in[8];
    const float* b_ih  = (const float*)d_in[9];
    const float* b_hh  = (const float*)d_in[10];
    const int*   ei    = (const int*)d_in[11];  // int32 view; dtype detected on device
    int E = in_sizes[11] / 2;
    float* out = (float*)d_out;

    int nb = (E + 255) / 256;
    if (nb > 4096) nb = 4096;

    k_reset  <<<1, 256>>>();
    k_detect <<<1, 256>>>(ei, E);
    k_collect<<<nb, 256>>>(ei, E);
    k_count  <<<nb, 256>>>(ei, E);
    k_gcn    <<<1, 256>>>(nf, W_enc, b_enc, W_gcn, b_gcn);
    k_gru    <<<192, 256>>>(W_ih, W_hh, b_ih, b_hh, h);
    k_out    <<<1, 256>>>(h, out);
}

// round 2
// speedup vs baseline: 1.3356x; 1.3356x over previous
#include <cuda_runtime.h>

// ============================================================================
// STGCNEncoder — only row 0 of the GCN output feeds the GRU. Compute exactly
// that: one streaming pass over dst builds a full degree histogram (spread
// atomics into an L2-resident 400KB table) AND collects the ~32 edges into
// node 0. Then tiny fused GEMVs for encoder/GCN-row0/GRU.
// ============================================================================

#define CAP 2048          // capacity for dst==0 edge list (expected ~32)
#define NMAX 131072       // degree table capacity (N = 100000)

__device__ int   g_is64;          // 1 if edge_index is int64, 0 if int32
__device__ int   g_cnt;           // number of dst==0 edges collected
__device__ int   g_srcs[CAP];     // src node of each dst==0 edge
__device__ int   g_deg[NMAX];     // edge in-degree histogram (self-loop NOT included)
__device__ float g_g0[128];       // relu(agg[0] + b_gcn)
__device__ float g_gi[768];
__device__ float g_gh[768];

// ---------------------------------------------------------------------------
// Zero the degree table + scalars. Grid-strided.
__global__ void k_reset(int n) {
    long gid = (long)blockIdx.x * blockDim.x + threadIdx.x;
    if (gid == 0) { g_cnt = 0; g_is64 = 1; }
    long stride = (long)gridDim.x * blockDim.x;
    for (long i = gid; i < n; i += stride) g_deg[i] = 0;
}

// Detect dtype: if data is int64 (values in [0,1e5)), every odd 32-bit word
// is 0. If int32, odd words are random node ids — some nonzero w.p. ~1-1e-2500.
__global__ void k_detect(const int* __restrict__ w, int E) {
    int i = threadIdx.x;
    int bad = 0;
    if (w[2 * i + 1] != 0) bad = 1;
    if (w[2 * (i + 256) + 1] != 0) bad = 1;
    if (bad) atomicAnd(&g_is64, 0);
}

// THE streaming pass: histogram every dst (spread atomics, L2-resident table)
// and collect src of dst==0 edges. Vectorized 16B loads.
__global__ void k_main(const int* __restrict__ w, int E) {
    long gid = (long)blockIdx.x * blockDim.x + threadIdx.x;
    long stride = (long)gridDim.x * blockDim.x;
    if (g_is64) {
        const long long* src = (const long long*)w;
        const long long* dst = src + E;
        int n2 = E >> 1;
        const longlong2* dst2 = (const longlong2*)dst;
        for (long i = gid; i < n2; i += stride) {
            longlong2 v = dst2[i];
            int d0 = (int)v.x, d1 = (int)v.y;
            atomicAdd(&g_deg[d0], 1);
            atomicAdd(&g_deg[d1], 1);
            if (d0 == 0) {
                int p = atomicAdd(&g_cnt, 1);
                if (p < CAP) g_srcs[p] = (int)src[2 * i];
            }
            if (d1 == 0) {
                int p = atomicAdd(&g_cnt, 1);
                if (p < CAP) g_srcs[p] = (int)src[2 * i + 1];
            }
        }
        // tail (E odd)
        if (gid == 0 && (E & 1)) {
            int d = (int)dst[E - 1];
            atomicAdd(&g_deg[d], 1);
            if (d == 0) {
                int p = atomicAdd(&g_cnt, 1);
                if (p < CAP) g_srcs[p] = (int)src[E - 1];
            }
        }
    } else {
        const int* src = w;
        const int* dst = w + E;
        int n4 = E >> 2;
        const int4* dst4 = (const int4*)dst;
        for (long i = gid; i < n4; i += stride) {
            int4 v = dst4[i];
            atomicAdd(&g_deg[v.x], 1);
            atomicAdd(&g_deg[v.y], 1);
            atomicAdd(&g_deg[v.z], 1);
            atomicAdd(&g_deg[v.w], 1);
            int d[4] = {v.x, v.y, v.z, v.w};
            #pragma unroll
            for (int k = 0; k < 4; k++) {
                if (d[k] == 0) {
                    int p = atomicAdd(&g_cnt, 1);
                    if (p < CAP) g_srcs[p] = src[4 * i + k];
                }
            }
        }
        if (gid < (E & 3)) {
            long i = (long)(E & ~3) + gid;
            int dd = dst[i];
            atomicAdd(&g_deg[dd], 1);
            if (dd == 0) {
                int p = atomicAdd(&g_cnt, 1);
                if (p < CAP) g_srcs[p] = src[i];
            }
        }
    }
}

// Encoder + weighted sum + GCN GEMV for row 0. Single block, 256 threads.
// xsum = sum_i w_i * relu(W_enc @ f[s_i] + b_enc),  w_i = rsqrt(deg_i)*rsqrt(deg_0)
// g0 = relu(W_gcn @ xsum + b_gcn)
__global__ void k_gcn(const float* __restrict__ nf,
                      const float* __restrict__ W_enc,
                      const float* __restrict__ b_enc,
                      const float* __restrict__ W_gcn,
                      const float* __restrict__ b_gcn) {
    __shared__ float sWe[128 * 65];   // W_enc padded (stride 65 -> conflict-free)
    __shared__ float sPart[8][128];   // per-warp partial xsum
    __shared__ float sF[8][64];       // per-warp node feature buffer
    __shared__ float sXsum[128];
    __shared__ float sBenc[128];

    int t = threadIdx.x, lane = t & 31, w = t >> 5;

    for (int i = t; i < 128 * 64; i += 256) {
        int j = i >> 6, k = i & 63;
        sWe[j * 65 + k] = W_enc[i];
    }
    if (t < 128) sBenc[t] = b_enc[t];
    for (int i = t; i < 8 * 128; i += 256) ((float*)sPart)[i] = 0.0f;
    __syncthreads();

    int cnt = g_cnt; if (cnt > CAP) cnt = CAP;
    int M = cnt + 1;                               // + node 0 self-loop term
    float dinv0 = rsqrtf((float)g_deg[0] + 1.0f);  // +1 self loop

    for (int i = w; i < M; i += 8) {
        int s = (i < cnt) ? g_srcs[i] : 0;
        float wt = rsqrtf((float)g_deg[s] + 1.0f) * dinv0;
        sF[w][lane]      = nf[(long)s * 64 + lane];
        sF[w][lane + 32] = nf[(long)s * 64 + 32 + lane];
        __syncwarp();
        #pragma unroll
        for (int jj = 0; jj < 4; jj++) {
            int j = jj * 32 + lane;
            float acc = sBenc[j];
            const float* wr = &sWe[j * 65];
            #pragma unroll
            for (int k = 0; k < 64; k++) acc += wr[k] * sF[w][k];
            sPart[w][j] += wt * fmaxf(acc, 0.0f);
        }
        __syncwarp();
    }
    __syncthreads();

    if (t < 128) {
        float xs = 0.0f;
        #pragma unroll
        for (int ww = 0; ww < 8; ww++) xs += sPart[ww][t];
        sXsum[t] = xs;
    }
    __syncthreads();

    // GCN GEMV: warp per output row, coalesced W_gcn reads + shuffle reduce
    for (int j = w; j < 128; j += 8) {
        float a = 0.0f;
        #pragma unroll
        for (int kk = 0; kk < 4; kk++) {
            int k = kk * 32 + lane;
            a += W_gcn[j * 128 + k] * sXsum[k];
        }
        #pragma unroll
        for (int off = 16; off; off >>= 1) a += __shfl_down_sync(0xffffffffu, a, off);
        if (lane == 0) g_g0[j] = fmaxf(a + b_gcn[j], 0.0f);
    }
}

// GRU GEMVs: 1536 warp-tasks (768 rows of W_ih@g0, 768 rows of W_hh@h).
__global__ void k_gru(const float* __restrict__ W_ih,
                      const float* __restrict__ W_hh,
                      const float* __restrict__ b_ih,
                      const float* __restrict__ b_hh,
                      const float* __restrict__ h) {
    __shared__ float sg0[128];
    int t = threadIdx.x, lane = t & 31, w = t >> 5;
    if (t < 128) sg0[t] = g_g0[t];
    __syncthreads();

    int task = blockIdx.x * 8 + w;
    if (task < 768) {
        const float* wr = W_ih + task * 128;
        float a = 0.0f;
        #pragma unroll
        for (int kk = 0; kk < 4; kk++) {
            int k = kk * 32 + lane;
            a += wr[k] * sg0[k];
        }
        #pragma unroll
        for (int off = 16; off; off >>= 1) a += __shfl_down_sync(0xffffffffu, a, off);
        if (lane == 0) g_gi[task] = a + b_ih[task];
    } else {
        int r = task - 768;
        const float* wr = W_hh + r * 256;
        float a = 0.0f;
        #pragma unroll
        for (int kk = 0; kk < 8; kk++) {
            int k = kk * 32 + lane;
            a += wr[k] * h[k];
        }
        #pragma unroll
        for (int off = 16; off; off >>= 1) a += __shfl_down_sync(0xffffffffu, a, off);
        if (lane == 0) g_gh[r] = a + b_hh[r];
    }
}

// Final gates.
__global__ void k_out(const float* __restrict__ h, float* __restrict__ out) {
    int c = threadIdx.x;
    float r  = 1.0f / (1.0f + expf(-(g_gi[c]       + g_gh[c])));
    float z  = 1.0f / (1.0f + expf(-(g_gi[256 + c] + g_gh[256 + c])));
    float nn = tanhf(g_gi[512 + c] + r * g_gh[512 + c]);
    out[c] = (1.0f - z) * nn + z * h[c];
}

// ---------------------------------------------------------------------------
extern "C" void kernel_launch(void* const* d_in, const int* in_sizes, int n_in,
                              void* d_out, int out_size) {
    const float* nf    = (const float*)d_in[0];
    // d_in[1] = edge_attr (unused by reference)
    const float* h     = (const float*)d_in[2];
    const float* W_enc = (const float*)d_in[3];
    const float* b_enc = (const float*)d_in[4];
    const float* W_gcn = (const float*)d_in[5];
    const float* b_gcn = (const float*)d_in[6];
    const float* W_ih  = (const float*)d_in[7];
    const float* W_hh  = (const float*)d_in[8];
    const float* b_ih  = (const float*)d_in[9];
    const float* b_hh  = (const float*)d_in[10];
    const int*   ei    = (const int*)d_in[11];  // int32 view; dtype detected on device
    int E = in_sizes[11] / 2;
    int n = in_sizes[0] / 64;
    if (n > NMAX) n = NMAX;
    float* out = (float*)d_out;

    int nb = (E / 2 + 255) / 256;
    if (nb > 2048) nb = 2048;

    k_reset  <<<256, 256>>>(n);
    k_detect <<<1, 256>>>(ei, E);
    k_main   <<<nb, 256>>>(ei, E);
    k_gcn    <<<1, 256>>>(nf, W_enc, b_enc, W_gcn, b_gcn);
    k_gru    <<<192, 256>>>(W_ih, W_hh, b_ih, b_hh, h);
    k_out    <<<1, 256>>>(h, out);
}